// round 12
// baseline (speedup 1.0000x reference)
#include <cuda_runtime.h>
#include <cuda_bf16.h>

// NeRF volume-rendering composite — converged final (R2/R7-R11 configuration).
// Inputs (metadata order):
//   0: sigma_vals [N, S] f32   1: rgb_vals [N, S, 3] f32   2: dists [N, S] f32
//   3: z_vals [N, S] f32       4: bg_color [N, 3] f32
// Output: [N, 4] f32 (r, g, b, depth)
//
// One warp per ray; lane l owns samples [4l, 4l+4) -> all bulk loads are
// fully-coalesced LDG.128 streams with __ldcs (read-once, evict-first:
// 203 MB streamed through a 126 MB L2, don't fight for residency).
// 256-thread one-shot blocks, regs=32 (load-bearing: 2048 thr/SM), occ ~91%.
//
// FINAL VERDICT (11 rounds): kernel pinned at 32.5-33.9 us = 6.1-6.35 TB/s
// against GB300's path-independent LTS chip cap (identical ceiling for
// LDG/LDG.cv/TMA). Traffic is single-touch and irreducible -> floor
// ~31.8 us; this kernel runs at ~96-98% of it. Five identical-source
// runs bound the noise: kernel sigma ~0.5 us, dur sigma ~0.6 us,
// uncorrelated with source. Swept and rejected: prefetch pipeline
// (R3: regs 64, occ 49%, +1.8us), persistent grid (R4: +2.2us),
// 128-thr blocks (R5: +0.4us), parallel epilogue / recombination
// (R5/R6: neutral-to-worse). No remaining lever exceeds the noise floor.

#ifndef NSAMP
#define NSAMP 128
#endif

__global__ __launch_bounds__(256, 4) void raymarch_kernel(
    const float* __restrict__ sigma,
    const float* __restrict__ rgb,
    const float* __restrict__ dists,
    const float* __restrict__ z_vals,
    const float* __restrict__ bg,
    float* __restrict__ out,
    int n_rays)
{
    const int warp_in_block = threadIdx.x >> 5;
    const int lane = threadIdx.x & 31;
    const int ray = blockIdx.x * (blockDim.x >> 5) + warp_in_block;
    if (ray >= n_rays) return;

    const unsigned FULL = 0xFFFFFFFFu;

    const float4* sig4 = reinterpret_cast<const float4*>(sigma  + (size_t)ray * NSAMP);
    const float4* dst4 = reinterpret_cast<const float4*>(dists  + (size_t)ray * NSAMP);
    const float4* zv4  = reinterpret_cast<const float4*>(z_vals + (size_t)ray * NSAMP);
    const float4* rg4  = reinterpret_cast<const float4*>(rgb    + (size_t)ray * NSAMP * 3);

    // ---- front-batched streaming loads: 6 independent LDG.128 in flight ----
    float4 s  = __ldcs(&sig4[lane]);
    float4 d  = __ldcs(&dst4[lane]);
    float4 z  = __ldcs(&zv4[lane]);
    float4 r0 = __ldcs(&rg4[3 * lane + 0]);   // s0.r s0.g s0.b s1.r
    float4 r1 = __ldcs(&rg4[3 * lane + 1]);   // s1.g s1.b s2.r s2.g
    float4 r2 = __ldcs(&rg4[3 * lane + 2]);   // s2.b s3.r s3.g s3.b

    // ---- alpha and (1 - alpha + eps) per sample ----
    float a0, a1, a2, a3;
    float t0, t1, t2, t3;
    {
        float tau;
        tau = fmaxf(s.x, 0.0f) * d.x;  a0 = 1.0f - __expf(-tau);  t0 = 1.0f - a0 + 1e-10f;
        tau = fmaxf(s.y, 0.0f) * d.y;  a1 = 1.0f - __expf(-tau);  t1 = 1.0f - a1 + 1e-10f;
        tau = fmaxf(s.z, 0.0f) * d.z;  a2 = 1.0f - __expf(-tau);  t2 = 1.0f - a2 + 1e-10f;
        tau = fmaxf(s.w, 0.0f) * d.w;  a3 = 1.0f - __expf(-tau);  t3 = 1.0f - a3 + 1e-10f;
    }

    // ---- local inclusive products ----
    float q0 = t0;
    float q1 = q0 * t1;
    float q2 = q1 * t2;
    float q3 = q2 * t3;   // product of this lane's 4 terms

    // ---- multiplicative inclusive warp scan of q3 ----
    float incl = q3;
    #pragma unroll
    for (int off = 1; off < 32; off <<= 1) {
        float v = __shfl_up_sync(FULL, incl, off);
        if (lane >= off) incl *= v;
    }
    // exclusive prefix (transmittance entering this lane's first sample)
    float excl = __shfl_up_sync(FULL, incl, 1);
    if (lane == 0) excl = 1.0f;

    // transmittance over ALL samples (no_hit) = lane 31's inclusive product
    float no_hit = __shfl_sync(FULL, incl, 31);

    // ---- weights and accumulation ----
    float w0 = a0 * excl;
    float w1 = a1 * (excl * q0);
    float w2 = a2 * (excl * q1);
    float w3 = a3 * (excl * q2);

    float cr = w0 * r0.x + w1 * r0.w + w2 * r1.z + w3 * r2.y;
    float cg = w0 * r0.y + w1 * r1.x + w2 * r1.w + w3 * r2.z;
    float cb = w0 * r0.z + w1 * r1.y + w2 * r2.x + w3 * r2.w;
    float dep = w0 * z.x + w1 * z.y + w2 * z.z + w3 * z.w;

    // ---- butterfly reductions (4 chains interleaved for ILP) ----
    #pragma unroll
    for (int off = 16; off > 0; off >>= 1) {
        cr  += __shfl_xor_sync(FULL, cr,  off);
        cg  += __shfl_xor_sync(FULL, cg,  off);
        cb  += __shfl_xor_sync(FULL, cb,  off);
        dep += __shfl_xor_sync(FULL, dep, off);
    }

    if (lane == 0) {
        const float* bgp = bg + (size_t)ray * 3;
        float4 o;
        o.x = cr + no_hit * __ldg(&bgp[0]);
        o.y = cg + no_hit * __ldg(&bgp[1]);
        o.z = cb + no_hit * __ldg(&bgp[2]);
        o.w = dep;
        __stcs(&reinterpret_cast<float4*>(out)[ray], o);
    }
}

extern "C" void kernel_launch(void* const* d_in, const int* in_sizes, int n_in,
                              void* d_out, int out_size) {
    const float* sigma  = (const float*)d_in[0];
    const float* rgb    = (const float*)d_in[1];
    const float* dists  = (const float*)d_in[2];
    const float* z_vals = (const float*)d_in[3];
    const float* bg     = (const float*)d_in[4];
    float* out = (float*)d_out;

    int n_rays = in_sizes[4] / 3;          // bg_color is [N, 3]
    int warps_per_block = 256 / 32;        // 8 rays per block
    int blocks = (n_rays + warps_per_block - 1) / warps_per_block;
    raymarch_kernel<<<blocks, 256>>>(sigma, rgb, dists, z_vals, bg, out, n_rays);
}

// round 13
// speedup vs baseline: 1.0404x; 1.0404x over previous
#include <cuda_runtime.h>
#include <cuda_bf16.h>

// NeRF volume-rendering composite — converged core, block=512 variant.
// Inputs (metadata order):
//   0: sigma_vals [N, S] f32   1: rgb_vals [N, S, 3] f32   2: dists [N, S] f32
//   3: z_vals [N, S] f32       4: bg_color [N, 3] f32
// Output: [N, 4] f32 (r, g, b, depth)
//
// One warp per ray; lane l owns samples [4l, 4l+4) -> all bulk loads are
// fully-coalesced LDG.128 streams with __ldcs (read-once, evict-first).
// R12 experiment: 512-thread blocks (16 warps) — same regs=32 and
// 2048 thr/SM, but half the block-scheduling events vs 256. This is the
// last unswept point on the only axis that showed measurable sensitivity
// (128thr: +0.4us) and carries zero regalloc risk.
//
// Kernel is otherwise pinned at ~6.1-6.35 TB/s = GB300 path-independent
// LTS chip cap; traffic single-touch/irreducible; floor ~31.8 us.

#ifndef NSAMP
#define NSAMP 128
#endif

__global__ __launch_bounds__(512, 2) void raymarch_kernel(
    const float* __restrict__ sigma,
    const float* __restrict__ rgb,
    const float* __restrict__ dists,
    const float* __restrict__ z_vals,
    const float* __restrict__ bg,
    float* __restrict__ out,
    int n_rays)
{
    const int warp_in_block = threadIdx.x >> 5;
    const int lane = threadIdx.x & 31;
    const int ray = blockIdx.x * (blockDim.x >> 5) + warp_in_block;
    if (ray >= n_rays) return;

    const unsigned FULL = 0xFFFFFFFFu;

    const float4* sig4 = reinterpret_cast<const float4*>(sigma  + (size_t)ray * NSAMP);
    const float4* dst4 = reinterpret_cast<const float4*>(dists  + (size_t)ray * NSAMP);
    const float4* zv4  = reinterpret_cast<const float4*>(z_vals + (size_t)ray * NSAMP);
    const float4* rg4  = reinterpret_cast<const float4*>(rgb    + (size_t)ray * NSAMP * 3);

    // ---- front-batched streaming loads: 6 independent LDG.128 in flight ----
    float4 s  = __ldcs(&sig4[lane]);
    float4 d  = __ldcs(&dst4[lane]);
    float4 z  = __ldcs(&zv4[lane]);
    float4 r0 = __ldcs(&rg4[3 * lane + 0]);   // s0.r s0.g s0.b s1.r
    float4 r1 = __ldcs(&rg4[3 * lane + 1]);   // s1.g s1.b s2.r s2.g
    float4 r2 = __ldcs(&rg4[3 * lane + 2]);   // s2.b s3.r s3.g s3.b

    // ---- alpha and (1 - alpha + eps) per sample ----
    float a0, a1, a2, a3;
    float t0, t1, t2, t3;
    {
        float tau;
        tau = fmaxf(s.x, 0.0f) * d.x;  a0 = 1.0f - __expf(-tau);  t0 = 1.0f - a0 + 1e-10f;
        tau = fmaxf(s.y, 0.0f) * d.y;  a1 = 1.0f - __expf(-tau);  t1 = 1.0f - a1 + 1e-10f;
        tau = fmaxf(s.z, 0.0f) * d.z;  a2 = 1.0f - __expf(-tau);  t2 = 1.0f - a2 + 1e-10f;
        tau = fmaxf(s.w, 0.0f) * d.w;  a3 = 1.0f - __expf(-tau);  t3 = 1.0f - a3 + 1e-10f;
    }

    // ---- local inclusive products ----
    float q0 = t0;
    float q1 = q0 * t1;
    float q2 = q1 * t2;
    float q3 = q2 * t3;   // product of this lane's 4 terms

    // ---- multiplicative inclusive warp scan of q3 ----
    float incl = q3;
    #pragma unroll
    for (int off = 1; off < 32; off <<= 1) {
        float v = __shfl_up_sync(FULL, incl, off);
        if (lane >= off) incl *= v;
    }
    // exclusive prefix (transmittance entering this lane's first sample)
    float excl = __shfl_up_sync(FULL, incl, 1);
    if (lane == 0) excl = 1.0f;

    // transmittance over ALL samples (no_hit) = lane 31's inclusive product
    float no_hit = __shfl_sync(FULL, incl, 31);

    // ---- weights and accumulation ----
    float w0 = a0 * excl;
    float w1 = a1 * (excl * q0);
    float w2 = a2 * (excl * q1);
    float w3 = a3 * (excl * q2);

    float cr = w0 * r0.x + w1 * r0.w + w2 * r1.z + w3 * r2.y;
    float cg = w0 * r0.y + w1 * r1.x + w2 * r1.w + w3 * r2.z;
    float cb = w0 * r0.z + w1 * r1.y + w2 * r2.x + w3 * r2.w;
    float dep = w0 * z.x + w1 * z.y + w2 * z.z + w3 * z.w;

    // ---- butterfly reductions (4 chains interleaved for ILP) ----
    #pragma unroll
    for (int off = 16; off > 0; off >>= 1) {
        cr  += __shfl_xor_sync(FULL, cr,  off);
        cg  += __shfl_xor_sync(FULL, cg,  off);
        cb  += __shfl_xor_sync(FULL, cb,  off);
        dep += __shfl_xor_sync(FULL, dep, off);
    }

    if (lane == 0) {
        const float* bgp = bg + (size_t)ray * 3;
        float4 o;
        o.x = cr + no_hit * __ldg(&bgp[0]);
        o.y = cg + no_hit * __ldg(&bgp[1]);
        o.z = cb + no_hit * __ldg(&bgp[2]);
        o.w = dep;
        __stcs(&reinterpret_cast<float4*>(out)[ray], o);
    }
}

extern "C" void kernel_launch(void* const* d_in, const int* in_sizes, int n_in,
                              void* d_out, int out_size) {
    const float* sigma  = (const float*)d_in[0];
    const float* rgb    = (const float*)d_in[1];
    const float* dists  = (const float*)d_in[2];
    const float* z_vals = (const float*)d_in[3];
    const float* bg     = (const float*)d_in[4];
    float* out = (float*)d_out;

    int n_rays = in_sizes[4] / 3;          // bg_color is [N, 3]
    int threads = 512;                     // 16 warps = 16 rays per block
    int warps_per_block = threads / 32;
    int blocks = (n_rays + warps_per_block - 1) / warps_per_block;
    raymarch_kernel<<<blocks, threads>>>(sigma, rgb, dists, z_vals, bg, out, n_rays);
}